// round 3
// baseline (speedup 1.0000x reference)
#include <cuda_runtime.h>

#define NUM_G 1024
#define HID 256
#define OUTW 768

// Flag: 1 if batch buffer is int64, 0 if int32. Set by probe kernel.
__device__ int d_batch_is64;

// Probe: look at 64 int32 words starting at word index n_nodes/2 (safe in both
// interpretations: int32 -> N words total, int64 -> 2N words). Sorted int32
// segment-ids there are ~NUM_G/2 (nonzero); an int64 view has every odd word 0.
__global__ void probe_batch_dtype(const int* __restrict__ b32, int n_nodes) {
    int zeros = 0;
    int base = n_nodes / 2;
    for (int i = 0; i < 64; i++)
        if (b32[base + i] == 0) zeros++;
    d_batch_is64 = (zeros > 16) ? 1 : 0;
}

__global__ __launch_bounds__(256)
void ensemble_pool_kernel(const float* __restrict__ x,
                          const void* __restrict__ batch_raw,
                          const float* __restrict__ att_w,
                          const float* __restrict__ att_b,
                          float* __restrict__ out,
                          int n_nodes) {
    __shared__ float s_part[8][HID];
    __shared__ int s_bounds[2];

    const int g = blockIdx.x;

    // Segment boundaries via binary search (batch is sorted). Threads 0/1 in parallel.
    if (threadIdx.x < 2) {
        const int is64 = d_batch_is64;
        const long long target = (long long)(g + (int)threadIdx.x);
        const int* b32 = (const int*)batch_raw;
        const long long* b64 = (const long long*)batch_raw;
        int lo = 0, hi = n_nodes;
        while (lo < hi) {
            int mid = (lo + hi) >> 1;
            long long v = is64 ? b64[mid] : (long long)b32[mid];
            if (v < target) lo = mid + 1; else hi = mid;
        }
        s_bounds[threadIdx.x] = lo;
    }
    __syncthreads();
    const int start = s_bounds[0];
    const int end   = s_bounds[1];

    const int warp = threadIdx.x >> 5;
    const int lane = threadIdx.x & 31;

    // Attention weights resident in registers: lane owns cols [4*lane..+3] and [128+4*lane..+3]
    const float4 w0 = reinterpret_cast<const float4*>(att_w)[lane];
    const float4 w1 = reinterpret_cast<const float4*>(att_w)[lane + 32];
    const float bias = att_b[0];

    const float NEG_INF = -__int_as_float(0x7f800000); // -inf

    float4 sum0 = make_float4(0.f, 0.f, 0.f, 0.f);
    float4 sum1 = make_float4(0.f, 0.f, 0.f, 0.f);
    float4 att0 = make_float4(0.f, 0.f, 0.f, 0.f);
    float4 att1 = make_float4(0.f, 0.f, 0.f, 0.f);
    float4 mx0  = make_float4(NEG_INF, NEG_INF, NEG_INF, NEG_INF);
    float4 mx1  = make_float4(NEG_INF, NEG_INF, NEG_INF, NEG_INF);

    // Mainloop: each warp independent, no block syncs. Coalesced 1KB row loads.
    for (int node = start + warp; node < end; node += 8) {
        const float4* row = reinterpret_cast<const float4*>(x + (size_t)node * HID);
        const float4 v0 = row[lane];
        const float4 v1 = row[lane + 32];

        // partial dot with attention vector
        float p = v0.x * w0.x + v0.y * w0.y + v0.z * w0.z + v0.w * w0.w
                + v1.x * w1.x + v1.y * w1.y + v1.z * w1.z + v1.w * w1.w;
        #pragma unroll
        for (int off = 16; off > 0; off >>= 1)
            p += __shfl_xor_sync(0xffffffffu, p, off);

        const float wt = 1.0f / (1.0f + __expf(-(p + bias)));

        sum0.x += v0.x; sum0.y += v0.y; sum0.z += v0.z; sum0.w += v0.w;
        sum1.x += v1.x; sum1.y += v1.y; sum1.z += v1.z; sum1.w += v1.w;

        mx0.x = fmaxf(mx0.x, v0.x); mx0.y = fmaxf(mx0.y, v0.y);
        mx0.z = fmaxf(mx0.z, v0.z); mx0.w = fmaxf(mx0.w, v0.w);
        mx1.x = fmaxf(mx1.x, v1.x); mx1.y = fmaxf(mx1.y, v1.y);
        mx1.z = fmaxf(mx1.z, v1.z); mx1.w = fmaxf(mx1.w, v1.w);

        att0.x = fmaf(v0.x, wt, att0.x); att0.y = fmaf(v0.y, wt, att0.y);
        att0.z = fmaf(v0.z, wt, att0.z); att0.w = fmaf(v0.w, wt, att0.w);
        att1.x = fmaf(v1.x, wt, att1.x); att1.y = fmaf(v1.y, wt, att1.y);
        att1.z = fmaf(v1.z, wt, att1.z); att1.w = fmaf(v1.w, wt, att1.w);
    }

    const float inv_cnt = 1.0f / fmaxf((float)(end - start), 1.0f);
    const int t = threadIdx.x;
    float* orow = out + (size_t)g * OUTW;

    // --- combine SUM (mean) ---
    reinterpret_cast<float4*>(&s_part[warp][4 * lane])[0]       = sum0;
    reinterpret_cast<float4*>(&s_part[warp][128 + 4 * lane])[0] = sum1;
    __syncthreads();
    {
        float acc = 0.f;
        #pragma unroll
        for (int w = 0; w < 8; w++) acc += s_part[w][t];
        orow[t] = acc * inv_cnt;
    }
    __syncthreads();

    // --- combine MAX ---
    reinterpret_cast<float4*>(&s_part[warp][4 * lane])[0]       = mx0;
    reinterpret_cast<float4*>(&s_part[warp][128 + 4 * lane])[0] = mx1;
    __syncthreads();
    {
        float acc = NEG_INF;
        #pragma unroll
        for (int w = 0; w < 8; w++) acc = fmaxf(acc, s_part[w][t]);
        orow[HID + t] = acc;
    }
    __syncthreads();

    // --- combine ATT ---
    reinterpret_cast<float4*>(&s_part[warp][4 * lane])[0]       = att0;
    reinterpret_cast<float4*>(&s_part[warp][128 + 4 * lane])[0] = att1;
    __syncthreads();
    {
        float acc = 0.f;
        #pragma unroll
        for (int w = 0; w < 8; w++) acc += s_part[w][t];
        orow[2 * HID + t] = acc;
    }
}

extern "C" void kernel_launch(void* const* d_in, const int* in_sizes, int n_in,
                              void* d_out, int out_size) {
    const float* x     = (const float*)d_in[0];
    const void*  batch = d_in[1];
    const float* att_w = (const float*)d_in[2];
    const float* att_b = (const float*)d_in[3];
    float*       out   = (float*)d_out;
    const int n_nodes = in_sizes[1];

    probe_batch_dtype<<<1, 1>>>((const int*)batch, n_nodes);
    ensemble_pool_kernel<<<NUM_G, 256>>>(x, batch, att_w, att_b, out, n_nodes);
}